// round 1
// baseline (speedup 1.0000x reference)
#include <cuda_runtime.h>
#include <math.h>

#define S_LEN 2048
#define DIM 2048
#define NH 32
#define NKV 8
#define HD 64
#define NREP 4
#define QK_SCALE 0.125f   // 1/sqrt(64)

// ---- scratch (device globals; no allocation allowed) ----
__device__ float g_q[S_LEN * NH * HD];    // [S, 2048]
__device__ float g_k[S_LEN * NKV * HD];   // [S, 512]
__device__ float g_v[S_LEN * NKV * HD];   // [S, 512]
__device__ float g_o[S_LEN * NH * HD];    // [S, 2048] attention output (sink-scaled)

// ============================================================================
// SGEMM NT: C[m,n] = sum_k A[m,k] * B[n,k] + bias[n]
// A: [M,K] row-major, B: [N,K] row-major. BM=BN=64, BK=32, 256 thr, 4x4/thread.
// ============================================================================
__global__ void __launch_bounds__(256) sgemm_nt_kernel(
    const float* __restrict__ A, const float* __restrict__ B,
    const float* __restrict__ bias, float* __restrict__ C,
    int M, int N, int K)
{
    __shared__ float As[32][68];   // [k][m], 68 keeps float4 alignment (272B rows)
    __shared__ float Bs[32][68];   // [k][n]

    const int tid = threadIdx.x;
    const int tx = tid & 15;       // n micro index
    const int ty = tid >> 4;       // m micro index
    const int m0 = blockIdx.y * 64;
    const int n0 = blockIdx.x * 64;

    float acc[4][4];
    #pragma unroll
    for (int i = 0; i < 4; i++)
        #pragma unroll
        for (int j = 0; j < 4; j++) acc[i][j] = 0.f;

    for (int kt = 0; kt < K; kt += 32) {
        // load 64x32 tiles of A and B, stored transposed into smem
        #pragma unroll
        for (int it = 0; it < 2; it++) {
            int e = tid + it * 256;      // 0..511 over [64 rows][8 float4]
            int row = e >> 3;
            int c4 = e & 7;
            float4 a = *(const float4*)(A + (size_t)(m0 + row) * K + kt + c4 * 4);
            As[c4 * 4 + 0][row] = a.x;
            As[c4 * 4 + 1][row] = a.y;
            As[c4 * 4 + 2][row] = a.z;
            As[c4 * 4 + 3][row] = a.w;
            float4 b = *(const float4*)(B + (size_t)(n0 + row) * K + kt + c4 * 4);
            Bs[c4 * 4 + 0][row] = b.x;
            Bs[c4 * 4 + 1][row] = b.y;
            Bs[c4 * 4 + 2][row] = b.z;
            Bs[c4 * 4 + 3][row] = b.w;
        }
        __syncthreads();

        #pragma unroll
        for (int k = 0; k < 32; k++) {
            const float4 av = *(const float4*)(&As[k][ty * 4]);
            const float4 bv = *(const float4*)(&Bs[k][tx * 4]);
            const float a0 = av.x, a1 = av.y, a2 = av.z, a3 = av.w;
            const float b0 = bv.x, b1 = bv.y, b2 = bv.z, b3 = bv.w;
            acc[0][0] = fmaf(a0, b0, acc[0][0]);
            acc[0][1] = fmaf(a0, b1, acc[0][1]);
            acc[0][2] = fmaf(a0, b2, acc[0][2]);
            acc[0][3] = fmaf(a0, b3, acc[0][3]);
            acc[1][0] = fmaf(a1, b0, acc[1][0]);
            acc[1][1] = fmaf(a1, b1, acc[1][1]);
            acc[1][2] = fmaf(a1, b2, acc[1][2]);
            acc[1][3] = fmaf(a1, b3, acc[1][3]);
            acc[2][0] = fmaf(a2, b0, acc[2][0]);
            acc[2][1] = fmaf(a2, b1, acc[2][1]);
            acc[2][2] = fmaf(a2, b2, acc[2][2]);
            acc[2][3] = fmaf(a2, b3, acc[2][3]);
            acc[3][0] = fmaf(a3, b0, acc[3][0]);
            acc[3][1] = fmaf(a3, b1, acc[3][1]);
            acc[3][2] = fmaf(a3, b2, acc[3][2]);
            acc[3][3] = fmaf(a3, b3, acc[3][3]);
        }
        __syncthreads();
    }

    // epilogue: +bias, vectorized store
    const int n = n0 + tx * 4;
    const float4 bv = *(const float4*)(bias + n);
    #pragma unroll
    for (int i = 0; i < 4; i++) {
        const int m = m0 + ty * 4 + i;
        float4 o;
        o.x = acc[i][0] + bv.x;
        o.y = acc[i][1] + bv.y;
        o.z = acc[i][2] + bv.z;
        o.w = acc[i][3] + bv.w;
        *(float4*)(C + (size_t)m * N + n) = o;
    }
}

// ============================================================================
// RoPE in-place on g_q and g_k.
// rope_cache[s, 0:32] = cos, rope_cache[s, 32:64] = sin.
// pair (d, d+32): x1' = x1*c - x2*s ; x2' = x1*s + x2*c
// ============================================================================
__global__ void rope_kernel(const float* __restrict__ rc)
{
    const int idx = blockIdx.x * blockDim.x + threadIdx.x;
    const int totalq = S_LEN * NH * 32;
    const int totalk = S_LEN * NKV * 32;
    if (idx < totalq) {
        const int d = idx & 31;
        const int sh = idx >> 5;
        const int h = sh & (NH - 1);
        const int s = sh >> 5;     // sh / NH, NH=32
        const float c = rc[s * HD + d];
        const float sn = rc[s * HD + 32 + d];
        float* p = g_q + ((size_t)s * NH + h) * HD;
        const float x1 = p[d], x2 = p[d + 32];
        p[d] = x1 * c - x2 * sn;
        p[d + 32] = x1 * sn + x2 * c;
    } else if (idx < totalq + totalk) {
        const int e = idx - totalq;
        const int d = e & 31;
        const int sh = e >> 5;
        const int h = sh & (NKV - 1);
        const int s = sh >> 3;     // sh / NKV, NKV=8
        const float c = rc[s * HD + d];
        const float sn = rc[s * HD + 32 + d];
        float* p = g_k + ((size_t)s * NKV + h) * HD;
        const float x1 = p[d], x2 = p[d + 32];
        p[d] = x1 * c - x2 * sn;
        p[d + 32] = x1 * sn + x2 * c;
    }
}

// ============================================================================
// Flash attention, causal, GQA, with attention-sink scaling.
// Grid: (S/128, NH). 128 threads/block, one query row per thread.
// K/V tiles of 64 rows in smem. Online softmax in 16-key chunks.
// Blocks run heaviest-first (reversed q0) to reduce causal tail imbalance.
// ============================================================================
__global__ void __launch_bounds__(128) flash_kernel(const float* __restrict__ sinks)
{
    __shared__ float ks[64][64];
    __shared__ float vs[64][64];

    const int h = blockIdx.y;
    const int kvh = h >> 2;            // NREP = 4
    const int q0 = ((int)gridDim.x - 1 - (int)blockIdx.x) * 128;
    const int r = q0 + threadIdx.x;

    // load q row (pre-scaled)
    float4 q4[16];
    {
        const float4* qp = (const float4*)(g_q + (size_t)r * (NH * HD) + h * HD);
        #pragma unroll
        for (int i = 0; i < 16; i++) {
            float4 t = qp[i];
            t.x *= QK_SCALE; t.y *= QK_SCALE; t.z *= QK_SCALE; t.w *= QK_SCALE;
            q4[i] = t;
        }
    }

    float acc[64];
    #pragma unroll
    for (int i = 0; i < 64; i++) acc[i] = 0.f;
    float m = -1e30f, l = 0.f;

    const int ntiles = q0 / 64 + 2;    // covers keys 0 .. q0+127
    for (int t = 0; t < ntiles; t++) {
        const int j0 = t * 64;
        __syncthreads();
        // cooperative load of K,V tile [64 x 64]
        #pragma unroll
        for (int it = 0; it < 8; it++) {
            const int e = threadIdx.x + it * 128;  // 0..1023 over [64][16 float4]
            const int row = e >> 4;
            const int c4 = e & 15;
            const size_t base = (size_t)(j0 + row) * (NKV * HD) + kvh * HD;
            *(float4*)&ks[row][c4 * 4] = *(const float4*)(g_k + base + c4 * 4);
            *(float4*)&vs[row][c4 * 4] = *(const float4*)(g_v + base + c4 * 4);
        }
        __syncthreads();

        #pragma unroll 1
        for (int c = 0; c < 4; c++) {
            // ---- 16 scores ----
            float sc[16];
            #pragma unroll
            for (int j = 0; j < 16; j++) {
                const int jj = c * 16 + j;
                const float4* kp = (const float4*)ks[jj];
                float s0 = 0.f, s1 = 0.f, s2 = 0.f, s3 = 0.f;
                #pragma unroll
                for (int i = 0; i < 16; i += 4) {
                    float4 k0 = kp[i + 0], k1 = kp[i + 1], k2 = kp[i + 2], k3 = kp[i + 3];
                    s0 = fmaf(q4[i + 0].x, k0.x, s0);
                    s0 = fmaf(q4[i + 0].y, k0.y, s0);
                    s0 = fmaf(q4[i + 0].z, k0.z, s0);
                    s0 = fmaf(q4[i + 0].w, k0.w, s0);
                    s1 = fmaf(q4[i + 1].x, k1.x, s1);
                    s1 = fmaf(q4[i + 1].y, k1.y, s1);
                    s1 = fmaf(q4[i + 1].z, k1.z, s1);
                    s1 = fmaf(q4[i + 1].w, k1.w, s1);
                    s2 = fmaf(q4[i + 2].x, k2.x, s2);
                    s2 = fmaf(q4[i + 2].y, k2.y, s2);
                    s2 = fmaf(q4[i + 2].z, k2.z, s2);
                    s2 = fmaf(q4[i + 2].w, k2.w, s2);
                    s3 = fmaf(q4[i + 3].x, k3.x, s3);
                    s3 = fmaf(q4[i + 3].y, k3.y, s3);
                    s3 = fmaf(q4[i + 3].z, k3.z, s3);
                    s3 = fmaf(q4[i + 3].w, k3.w, s3);
                }
                const float dot = (s0 + s1) + (s2 + s3);
                sc[j] = ((j0 + jj) <= r) ? dot : -1e30f;
            }

            // ---- online softmax update ----
            float cmax = sc[0];
            #pragma unroll
            for (int j = 1; j < 16; j++) cmax = fmaxf(cmax, sc[j]);
            const float mnew = fmaxf(m, cmax);
            const float alpha = __expf(m - mnew);
            m = mnew;
            l *= alpha;
            #pragma unroll
            for (int i = 0; i < 64; i++) acc[i] *= alpha;

            float p[16];
            #pragma unroll
            for (int j = 0; j < 16; j++) {
                p[j] = __expf(sc[j] - mnew);
                l += p[j];
            }

            // ---- acc += p * V ----
            #pragma unroll
            for (int j = 0; j < 16; j++) {
                const float pj = p[j];
                const float4* vp = (const float4*)vs[c * 16 + j];
                #pragma unroll
                for (int i = 0; i < 16; i++) {
                    const float4 vv = vp[i];
                    acc[4 * i + 0] = fmaf(pj, vv.x, acc[4 * i + 0]);
                    acc[4 * i + 1] = fmaf(pj, vv.y, acc[4 * i + 1]);
                    acc[4 * i + 2] = fmaf(pj, vv.z, acc[4 * i + 2]);
                    acc[4 * i + 3] = fmaf(pj, vv.w, acc[4 * i + 3]);
                }
            }
        }
    }

    // epilogue: lse, sink sigmoid, normalize, store
    const float lse = m + __logf(l);
    const float sg = 1.f / (1.f + __expf(sinks[h] - lse));
    const float w = sg / l;
    float* op = g_o + (size_t)r * (NH * HD) + h * HD;
    #pragma unroll
    for (int i = 0; i < 16; i++) {
        float4 o;
        o.x = acc[4 * i + 0] * w;
        o.y = acc[4 * i + 1] * w;
        o.z = acc[4 * i + 2] * w;
        o.w = acc[4 * i + 3] * w;
        *(float4*)(op + 4 * i) = o;
    }
}

// ============================================================================
// launch
// ============================================================================
extern "C" void kernel_launch(void* const* d_in, const int* in_sizes, int n_in,
                              void* d_out, int out_size)
{
    const float* x     = (const float*)d_in[0];
    const float* rc    = (const float*)d_in[1];
    const float* wq_w  = (const float*)d_in[2];
    const float* wq_b  = (const float*)d_in[3];
    const float* wk_w  = (const float*)d_in[4];
    const float* wk_b  = (const float*)d_in[5];
    const float* wv_w  = (const float*)d_in[6];
    const float* wv_b  = (const float*)d_in[7];
    const float* wo_w  = (const float*)d_in[8];
    const float* wo_b  = (const float*)d_in[9];
    const float* sinks = (const float*)d_in[10];
    float* out = (float*)d_out;

    float *qp, *kp, *vp, *op;
    cudaGetSymbolAddress((void**)&qp, g_q);
    cudaGetSymbolAddress((void**)&kp, g_k);
    cudaGetSymbolAddress((void**)&vp, g_v);
    cudaGetSymbolAddress((void**)&op, g_o);

    // QKV projections
    sgemm_nt_kernel<<<dim3(DIM / 64, S_LEN / 64), 256>>>(x, wq_w, wq_b, qp, S_LEN, NH * HD, DIM);
    sgemm_nt_kernel<<<dim3((NKV * HD) / 64, S_LEN / 64), 256>>>(x, wk_w, wk_b, kp, S_LEN, NKV * HD, DIM);
    sgemm_nt_kernel<<<dim3((NKV * HD) / 64, S_LEN / 64), 256>>>(x, wv_w, wv_b, vp, S_LEN, NKV * HD, DIM);

    // RoPE on q and k
    {
        const int total = S_LEN * NH * 32 + S_LEN * NKV * 32;
        rope_kernel<<<(total + 255) / 256, 256>>>(rc);
    }

    // flash attention (+ sinks)
    flash_kernel<<<dim3(S_LEN / 128, NH), 128>>>(sinks);

    // output projection
    sgemm_nt_kernel<<<dim3(DIM / 64, S_LEN / 64), 256>>>(op, wo_w, wo_b, out, S_LEN, DIM, DIM);
}

// round 2
// speedup vs baseline: 1.5080x; 1.5080x over previous
#include <cuda_runtime.h>
#include <math.h>
#include <stdint.h>

#define S_LEN 2048
#define DIM 2048
#define NH 32
#define NKV 8
#define HD 64
#define NREP 4
#define QK_SCALE 0.125f   // 1/sqrt(64)

// ---- scratch (device globals; no allocation allowed) ----
__device__ float g_q[S_LEN * NH * HD];    // [S, 2048]
__device__ float g_k[S_LEN * NKV * HD];   // [S, 512]
__device__ float g_v[S_LEN * NKV * HD];   // [S, 512]
__device__ float g_o[S_LEN * NH * HD];    // [S, 2048] attention output (sink-scaled)

// ============================================================================
// TF32 tensor-core GEMM NT: C[m,n] = sum_k A[m,k]*B[n,k] + bias[n]
// Block 128x128x16, 8 warps, warp tile 32x64 (2x8 m16n8k8 mma tiles).
// Smem row stride 20 words -> conflict-free fragment LDS.
// ============================================================================
__device__ __forceinline__ uint32_t f2tf32(float f) {
    uint32_t t;
    asm("cvt.rna.tf32.f32 %0, %1;" : "=r"(t) : "f"(f));
    return t;
}

__device__ __forceinline__ void mma_tf32(float* c, const uint32_t* a, const uint32_t* b) {
    asm volatile(
        "mma.sync.aligned.m16n8k8.row.col.f32.tf32.tf32.f32 "
        "{%0,%1,%2,%3}, {%4,%5,%6,%7}, {%8,%9}, {%0,%1,%2,%3};"
        : "+f"(c[0]), "+f"(c[1]), "+f"(c[2]), "+f"(c[3])
        : "r"(a[0]), "r"(a[1]), "r"(a[2]), "r"(a[3]), "r"(b[0]), "r"(b[1]));
}

#define SMS 20   // smem row stride (16 + 4 pad)

__global__ void __launch_bounds__(256, 2) gemm_tf32_nt(
    const float* __restrict__ A, const float* __restrict__ B,
    const float* __restrict__ bias, float* __restrict__ C,
    int M, int N, int K)
{
    __shared__ uint32_t As[128 * SMS];
    __shared__ uint32_t Bs[128 * SMS];

    const int tid = threadIdx.x;
    const int m0 = blockIdx.y * 128;
    const int n0 = blockIdx.x * 128;

    const int wid = tid >> 5;
    const int wm = wid & 3;          // 4 warps along m
    const int wn = wid >> 2;         // 2 warps along n
    const int l = tid & 31;
    const int l4 = l >> 2;
    const int lk = l & 3;

    // global load coordinates: 64 rows per pass, 4 floats per thread per pass
    const int grow = tid >> 2;
    const int gk = (tid & 3) * 4;

    float acc[2][8][4];
    #pragma unroll
    for (int i = 0; i < 2; i++)
        #pragma unroll
        for (int j = 0; j < 8; j++)
            #pragma unroll
            for (int q = 0; q < 4; q++) acc[i][j][q] = 0.f;

    const float* Ab = A + (size_t)(m0 + grow) * K + gk;
    const float* Bb = B + (size_t)(n0 + grow) * K + gk;

    // initial prefetch (kt = 0)
    float4 pa0 = *(const float4*)(Ab);
    float4 pa1 = *(const float4*)(Ab + (size_t)64 * K);
    float4 pb0 = *(const float4*)(Bb);
    float4 pb1 = *(const float4*)(Bb + (size_t)64 * K);

    for (int kt = 0; kt < K; kt += 16) {
        // store current tiles to smem (converted to tf32)
        {
            uint32_t* pA = As + grow * SMS + gk;
            pA[0] = f2tf32(pa0.x); pA[1] = f2tf32(pa0.y);
            pA[2] = f2tf32(pa0.z); pA[3] = f2tf32(pa0.w);
            uint32_t* pA2 = pA + 64 * SMS;
            pA2[0] = f2tf32(pa1.x); pA2[1] = f2tf32(pa1.y);
            pA2[2] = f2tf32(pa1.z); pA2[3] = f2tf32(pa1.w);
            uint32_t* pB = Bs + grow * SMS + gk;
            pB[0] = f2tf32(pb0.x); pB[1] = f2tf32(pb0.y);
            pB[2] = f2tf32(pb0.z); pB[3] = f2tf32(pb0.w);
            uint32_t* pB2 = pB + 64 * SMS;
            pB2[0] = f2tf32(pb1.x); pB2[1] = f2tf32(pb1.y);
            pB2[2] = f2tf32(pb1.z); pB2[3] = f2tf32(pb1.w);
        }
        __syncthreads();

        // prefetch next tiles (overlaps with mma below)
        if (kt + 16 < K) {
            pa0 = *(const float4*)(Ab + kt + 16);
            pa1 = *(const float4*)(Ab + (size_t)64 * K + kt + 16);
            pb0 = *(const float4*)(Bb + kt + 16);
            pb1 = *(const float4*)(Bb + (size_t)64 * K + kt + 16);
        }

        // compute: 2 k-steps of 8
        #pragma unroll
        for (int k0 = 0; k0 < 16; k0 += 8) {
            uint32_t a[2][4], b[8][2];
            #pragma unroll
            for (int tm = 0; tm < 2; tm++) {
                const uint32_t* base = As + (wm * 32 + tm * 16 + l4) * SMS + k0 + lk;
                a[tm][0] = base[0];
                a[tm][1] = base[8 * SMS];
                a[tm][2] = base[4];
                a[tm][3] = base[8 * SMS + 4];
            }
            #pragma unroll
            for (int tn = 0; tn < 8; tn++) {
                const uint32_t* bb = Bs + (wn * 64 + tn * 8 + l4) * SMS + k0 + lk;
                b[tn][0] = bb[0];
                b[tn][1] = bb[4];
            }
            #pragma unroll
            for (int tm = 0; tm < 2; tm++)
                #pragma unroll
                for (int tn = 0; tn < 8; tn++)
                    mma_tf32(acc[tm][tn], a[tm], b[tn]);
        }
        __syncthreads();
    }

    // epilogue: +bias, float2 stores
    #pragma unroll
    for (int tm = 0; tm < 2; tm++) {
        const int row0 = m0 + wm * 32 + tm * 16 + l4;
        #pragma unroll
        for (int tn = 0; tn < 8; tn++) {
            const int col = n0 + wn * 64 + tn * 8 + lk * 2;
            const float b0 = bias[col];
            const float b1 = bias[col + 1];
            float2 v0 = make_float2(acc[tm][tn][0] + b0, acc[tm][tn][1] + b1);
            float2 v1 = make_float2(acc[tm][tn][2] + b0, acc[tm][tn][3] + b1);
            *(float2*)(C + (size_t)row0 * N + col) = v0;
            *(float2*)(C + (size_t)(row0 + 8) * N + col) = v1;
        }
    }
}

// ============================================================================
// RoPE in-place on g_q and g_k.
// ============================================================================
__global__ void rope_kernel(const float* __restrict__ rc)
{
    const int idx = blockIdx.x * blockDim.x + threadIdx.x;
    const int totalq = S_LEN * NH * 32;
    const int totalk = S_LEN * NKV * 32;
    if (idx < totalq) {
        const int d = idx & 31;
        const int sh = idx >> 5;
        const int h = sh & (NH - 1);
        const int s = sh >> 5;
        const float c = rc[s * HD + d];
        const float sn = rc[s * HD + 32 + d];
        float* p = g_q + ((size_t)s * NH + h) * HD;
        const float x1 = p[d], x2 = p[d + 32];
        p[d] = x1 * c - x2 * sn;
        p[d + 32] = x1 * sn + x2 * c;
    } else if (idx < totalq + totalk) {
        const int e = idx - totalq;
        const int d = e & 31;
        const int sh = e >> 5;
        const int h = sh & (NKV - 1);
        const int s = sh >> 3;
        const float c = rc[s * HD + d];
        const float sn = rc[s * HD + 32 + d];
        float* p = g_k + ((size_t)s * NKV + h) * HD;
        const float x1 = p[d], x2 = p[d + 32];
        p[d] = x1 * c - x2 * sn;
        p[d + 32] = x1 * sn + x2 * c;
    }
}

// ============================================================================
// Flash attention, causal, GQA, with attention-sink scaling. (unchanged)
// ============================================================================
__global__ void __launch_bounds__(128) flash_kernel(const float* __restrict__ sinks)
{
    __shared__ float ks[64][64];
    __shared__ float vs[64][64];

    const int h = blockIdx.y;
    const int kvh = h >> 2;
    const int q0 = ((int)gridDim.x - 1 - (int)blockIdx.x) * 128;
    const int r = q0 + threadIdx.x;

    float4 q4[16];
    {
        const float4* qp = (const float4*)(g_q + (size_t)r * (NH * HD) + h * HD);
        #pragma unroll
        for (int i = 0; i < 16; i++) {
            float4 t = qp[i];
            t.x *= QK_SCALE; t.y *= QK_SCALE; t.z *= QK_SCALE; t.w *= QK_SCALE;
            q4[i] = t;
        }
    }

    float acc[64];
    #pragma unroll
    for (int i = 0; i < 64; i++) acc[i] = 0.f;
    float m = -1e30f, l = 0.f;

    const int ntiles = q0 / 64 + 2;
    for (int t = 0; t < ntiles; t++) {
        const int j0 = t * 64;
        __syncthreads();
        #pragma unroll
        for (int it = 0; it < 8; it++) {
            const int e = threadIdx.x + it * 128;
            const int row = e >> 4;
            const int c4 = e & 15;
            const size_t base = (size_t)(j0 + row) * (NKV * HD) + kvh * HD;
            *(float4*)&ks[row][c4 * 4] = *(const float4*)(g_k + base + c4 * 4);
            *(float4*)&vs[row][c4 * 4] = *(const float4*)(g_v + base + c4 * 4);
        }
        __syncthreads();

        #pragma unroll 1
        for (int c = 0; c < 4; c++) {
            float sc[16];
            #pragma unroll
            for (int j = 0; j < 16; j++) {
                const int jj = c * 16 + j;
                const float4* kp = (const float4*)ks[jj];
                float s0 = 0.f, s1 = 0.f, s2 = 0.f, s3 = 0.f;
                #pragma unroll
                for (int i = 0; i < 16; i += 4) {
                    float4 k0 = kp[i + 0], k1 = kp[i + 1], k2 = kp[i + 2], k3 = kp[i + 3];
                    s0 = fmaf(q4[i + 0].x, k0.x, s0);
                    s0 = fmaf(q4[i + 0].y, k0.y, s0);
                    s0 = fmaf(q4[i + 0].z, k0.z, s0);
                    s0 = fmaf(q4[i + 0].w, k0.w, s0);
                    s1 = fmaf(q4[i + 1].x, k1.x, s1);
                    s1 = fmaf(q4[i + 1].y, k1.y, s1);
                    s1 = fmaf(q4[i + 1].z, k1.z, s1);
                    s1 = fmaf(q4[i + 1].w, k1.w, s1);
                    s2 = fmaf(q4[i + 2].x, k2.x, s2);
                    s2 = fmaf(q4[i + 2].y, k2.y, s2);
                    s2 = fmaf(q4[i + 2].z, k2.z, s2);
                    s2 = fmaf(q4[i + 2].w, k2.w, s2);
                    s3 = fmaf(q4[i + 3].x, k3.x, s3);
                    s3 = fmaf(q4[i + 3].y, k3.y, s3);
                    s3 = fmaf(q4[i + 3].z, k3.z, s3);
                    s3 = fmaf(q4[i + 3].w, k3.w, s3);
                }
                const float dot = (s0 + s1) + (s2 + s3);
                sc[j] = ((j0 + jj) <= r) ? dot : -1e30f;
            }

            float cmax = sc[0];
            #pragma unroll
            for (int j = 1; j < 16; j++) cmax = fmaxf(cmax, sc[j]);
            const float mnew = fmaxf(m, cmax);
            const float alpha = __expf(m - mnew);
            m = mnew;
            l *= alpha;
            #pragma unroll
            for (int i = 0; i < 64; i++) acc[i] *= alpha;

            float p[16];
            #pragma unroll
            for (int j = 0; j < 16; j++) {
                p[j] = __expf(sc[j] - mnew);
                l += p[j];
            }

            #pragma unroll
            for (int j = 0; j < 16; j++) {
                const float pj = p[j];
                const float4* vp = (const float4*)vs[c * 16 + j];
                #pragma unroll
                for (int i = 0; i < 16; i++) {
                    const float4 vv = vp[i];
                    acc[4 * i + 0] = fmaf(pj, vv.x, acc[4 * i + 0]);
                    acc[4 * i + 1] = fmaf(pj, vv.y, acc[4 * i + 1]);
                    acc[4 * i + 2] = fmaf(pj, vv.z, acc[4 * i + 2]);
                    acc[4 * i + 3] = fmaf(pj, vv.w, acc[4 * i + 3]);
                }
            }
        }
    }

    const float lse = m + __logf(l);
    const float sg = 1.f / (1.f + __expf(sinks[h] - lse));
    const float w = sg / l;
    float* op = g_o + (size_t)r * (NH * HD) + h * HD;
    #pragma unroll
    for (int i = 0; i < 16; i++) {
        float4 o;
        o.x = acc[4 * i + 0] * w;
        o.y = acc[4 * i + 1] * w;
        o.z = acc[4 * i + 2] * w;
        o.w = acc[4 * i + 3] * w;
        *(float4*)(op + 4 * i) = o;
    }
}

// ============================================================================
// launch
// ============================================================================
extern "C" void kernel_launch(void* const* d_in, const int* in_sizes, int n_in,
                              void* d_out, int out_size)
{
    const float* x     = (const float*)d_in[0];
    const float* rc    = (const float*)d_in[1];
    const float* wq_w  = (const float*)d_in[2];
    const float* wq_b  = (const float*)d_in[3];
    const float* wk_w  = (const float*)d_in[4];
    const float* wk_b  = (const float*)d_in[5];
    const float* wv_w  = (const float*)d_in[6];
    const float* wv_b  = (const float*)d_in[7];
    const float* wo_w  = (const float*)d_in[8];
    const float* wo_b  = (const float*)d_in[9];
    const float* sinks = (const float*)d_in[10];
    float* out = (float*)d_out;

    float *qp, *kp, *vp, *op;
    cudaGetSymbolAddress((void**)&qp, g_q);
    cudaGetSymbolAddress((void**)&kp, g_k);
    cudaGetSymbolAddress((void**)&vp, g_v);
    cudaGetSymbolAddress((void**)&op, g_o);

    // QKV projections (tf32 tensor cores)
    gemm_tf32_nt<<<dim3((NH * HD) / 128, S_LEN / 128), 256>>>(x, wq_w, wq_b, qp, S_LEN, NH * HD, DIM);
    gemm_tf32_nt<<<dim3((NKV * HD) / 128, S_LEN / 128), 256>>>(x, wk_w, wk_b, kp, S_LEN, NKV * HD, DIM);
    gemm_tf32_nt<<<dim3((NKV * HD) / 128, S_LEN / 128), 256>>>(x, wv_w, wv_b, vp, S_LEN, NKV * HD, DIM);

    // RoPE on q and k
    {
        const int total = S_LEN * NH * 32 + S_LEN * NKV * 32;
        rope_kernel<<<(total + 255) / 256, 256>>>(rc);
    }

    // flash attention (+ sinks)
    flash_kernel<<<dim3(S_LEN / 128, NH), 128>>>(sinks);

    // output projection (tf32 tensor cores)
    gemm_tf32_nt<<<dim3(DIM / 128, S_LEN / 128), 256>>>(op, wo_w, wo_b, out, S_LEN, DIM, DIM);
}

// round 3
// speedup vs baseline: 3.3790x; 2.2407x over previous
#include <cuda_runtime.h>
#include <math.h>
#include <stdint.h>

#define S_LEN 2048
#define DIM 2048
#define NH 32
#define NKV 8
#define HD 64
#define QK_SCALE 0.125f   // 1/sqrt(64)

// ---- scratch (device globals; no allocation allowed) ----
__device__ float g_q[S_LEN * NH * HD];
__device__ float g_k[S_LEN * NKV * HD];
__device__ float g_v[S_LEN * NKV * HD];
__device__ float g_o[S_LEN * NH * HD];

__device__ __forceinline__ uint32_t f2tf32(float f) {
    uint32_t t;
    asm("cvt.rna.tf32.f32 %0, %1;" : "=r"(t) : "f"(f));
    return t;
}

__device__ __forceinline__ void mma_tf32(float* c, const uint32_t* a, const uint32_t* b) {
    asm volatile(
        "mma.sync.aligned.m16n8k8.row.col.f32.tf32.tf32.f32 "
        "{%0,%1,%2,%3}, {%4,%5,%6,%7}, {%8,%9}, {%0,%1,%2,%3};"
        : "+f"(c[0]), "+f"(c[1]), "+f"(c[2]), "+f"(c[3])
        : "r"(a[0]), "r"(a[1]), "r"(a[2]), "r"(a[3]), "r"(b[0]), "r"(b[1]));
}

// ============================================================================
// TF32 GEMM NT core: C[m,n] = sum_k A[m,k]*B[n,k] + bias[n]
// Block 128x128x16, 8 warps, warp tile 32x64. Double-buffered smem,
// ONE __syncthreads per K-slab.
// ============================================================================
#define SMS 20

__device__ __forceinline__ void gemm_core(
    const float* __restrict__ A, const float* __restrict__ B,
    const float* __restrict__ bias, float* __restrict__ C,
    int N, int K, int m0, int n0)
{
    __shared__ uint32_t As[2][128 * SMS];
    __shared__ uint32_t Bs[2][128 * SMS];

    const int tid = threadIdx.x;
    const int wid = tid >> 5;
    const int wm = wid & 3;
    const int wn = wid >> 2;
    const int l = tid & 31;
    const int l4 = l >> 2;
    const int lk = l & 3;

    const int grow = tid >> 2;
    const int gk = (tid & 3) * 4;

    float acc[2][8][4];
    #pragma unroll
    for (int i = 0; i < 2; i++)
        #pragma unroll
        for (int j = 0; j < 8; j++)
            #pragma unroll
            for (int q = 0; q < 4; q++) acc[i][j][q] = 0.f;

    const float* Ab = A + (size_t)(m0 + grow) * K + gk;
    const float* Bb = B + (size_t)(n0 + grow) * K + gk;

    float4 pa0 = *(const float4*)(Ab);
    float4 pa1 = *(const float4*)(Ab + (size_t)64 * K);
    float4 pb0 = *(const float4*)(Bb);
    float4 pb1 = *(const float4*)(Bb + (size_t)64 * K);

    // store stage 0
    {
        uint32_t* pA = As[0] + grow * SMS + gk;
        pA[0] = f2tf32(pa0.x); pA[1] = f2tf32(pa0.y); pA[2] = f2tf32(pa0.z); pA[3] = f2tf32(pa0.w);
        uint32_t* pA2 = pA + 64 * SMS;
        pA2[0] = f2tf32(pa1.x); pA2[1] = f2tf32(pa1.y); pA2[2] = f2tf32(pa1.z); pA2[3] = f2tf32(pa1.w);
        uint32_t* pB = Bs[0] + grow * SMS + gk;
        pB[0] = f2tf32(pb0.x); pB[1] = f2tf32(pb0.y); pB[2] = f2tf32(pb0.z); pB[3] = f2tf32(pb0.w);
        uint32_t* pB2 = pB + 64 * SMS;
        pB2[0] = f2tf32(pb1.x); pB2[1] = f2tf32(pb1.y); pB2[2] = f2tf32(pb1.z); pB2[3] = f2tf32(pb1.w);
    }

    int cur = 0;
    for (int kt = 0; kt < K; kt += 16) {
        __syncthreads();
        const bool more = (kt + 16) < K;
        if (more) {
            pa0 = *(const float4*)(Ab + kt + 16);
            pa1 = *(const float4*)(Ab + (size_t)64 * K + kt + 16);
            pb0 = *(const float4*)(Bb + kt + 16);
            pb1 = *(const float4*)(Bb + (size_t)64 * K + kt + 16);
        }

        const uint32_t* Ac = As[cur];
        const uint32_t* Bc = Bs[cur];
        #pragma unroll
        for (int k0 = 0; k0 < 16; k0 += 8) {
            uint32_t a[2][4], b[8][2];
            #pragma unroll
            for (int tm = 0; tm < 2; tm++) {
                const uint32_t* base = Ac + (wm * 32 + tm * 16 + l4) * SMS + k0 + lk;
                a[tm][0] = base[0];
                a[tm][1] = base[8 * SMS];
                a[tm][2] = base[4];
                a[tm][3] = base[8 * SMS + 4];
            }
            #pragma unroll
            for (int tn = 0; tn < 8; tn++) {
                const uint32_t* bb = Bc + (wn * 64 + tn * 8 + l4) * SMS + k0 + lk;
                b[tn][0] = bb[0];
                b[tn][1] = bb[4];
            }
            #pragma unroll
            for (int tm = 0; tm < 2; tm++)
                #pragma unroll
                for (int tn = 0; tn < 8; tn++)
                    mma_tf32(acc[tm][tn], a[tm], b[tn]);
        }

        if (more) {
            const int nxt = cur ^ 1;
            uint32_t* pA = As[nxt] + grow * SMS + gk;
            pA[0] = f2tf32(pa0.x); pA[1] = f2tf32(pa0.y); pA[2] = f2tf32(pa0.z); pA[3] = f2tf32(pa0.w);
            uint32_t* pA2 = pA + 64 * SMS;
            pA2[0] = f2tf32(pa1.x); pA2[1] = f2tf32(pa1.y); pA2[2] = f2tf32(pa1.z); pA2[3] = f2tf32(pa1.w);
            uint32_t* pB = Bs[nxt] + grow * SMS + gk;
            pB[0] = f2tf32(pb0.x); pB[1] = f2tf32(pb0.y); pB[2] = f2tf32(pb0.z); pB[3] = f2tf32(pb0.w);
            uint32_t* pB2 = pB + 64 * SMS;
            pB2[0] = f2tf32(pb1.x); pB2[1] = f2tf32(pb1.y); pB2[2] = f2tf32(pb1.z); pB2[3] = f2tf32(pb1.w);
        }
        cur ^= 1;
    }

    #pragma unroll
    for (int tm = 0; tm < 2; tm++) {
        const int row0 = m0 + wm * 32 + tm * 16 + l4;
        #pragma unroll
        for (int tn = 0; tn < 8; tn++) {
            const int col = n0 + wn * 64 + tn * 8 + lk * 2;
            const float b0 = bias[col];
            const float b1 = bias[col + 1];
            float2 v0 = make_float2(acc[tm][tn][0] + b0, acc[tm][tn][1] + b1);
            float2 v1 = make_float2(acc[tm][tn][2] + b0, acc[tm][tn][3] + b1);
            *(float2*)(C + (size_t)row0 * N + col) = v0;
            *(float2*)(C + (size_t)(row0 + 8) * N + col) = v1;
        }
    }
}

__global__ void __launch_bounds__(256, 2) gemm_tf32_single(
    const float* __restrict__ A, const float* __restrict__ B,
    const float* __restrict__ bias, float* __restrict__ C, int N, int K)
{
    gemm_core(A, B, bias, C, N, K, blockIdx.y * 128, blockIdx.x * 128);
}

// fused K+V projection: blockIdx.z selects which GEMM
__global__ void __launch_bounds__(256, 2) gemm_tf32_kv(
    const float* __restrict__ A,
    const float* __restrict__ Bk, const float* __restrict__ bk, float* __restrict__ Ck,
    const float* __restrict__ Bv, const float* __restrict__ bv, float* __restrict__ Cv,
    int N, int K)
{
    const float* B = blockIdx.z ? Bv : Bk;
    const float* bias = blockIdx.z ? bv : bk;
    float* C = blockIdx.z ? Cv : Ck;
    gemm_core(A, B, bias, C, N, K, blockIdx.y * 128, blockIdx.x * 128);
}

// ============================================================================
// RoPE in-place on g_q and g_k.
// ============================================================================
__global__ void rope_kernel(const float* __restrict__ rc)
{
    const int idx = blockIdx.x * blockDim.x + threadIdx.x;
    const int totalq = S_LEN * NH * 32;
    const int totalk = S_LEN * NKV * 32;
    if (idx < totalq) {
        const int d = idx & 31;
        const int sh = idx >> 5;
        const int h = sh & (NH - 1);
        const int s = sh >> 5;
        const float c = rc[s * HD + d];
        const float sn = rc[s * HD + 32 + d];
        float* p = g_q + ((size_t)s * NH + h) * HD;
        const float x1 = p[d], x2 = p[d + 32];
        p[d] = x1 * c - x2 * sn;
        p[d + 32] = x1 * sn + x2 * c;
    } else if (idx < totalq + totalk) {
        const int e = idx - totalq;
        const int d = e & 31;
        const int sh = e >> 5;
        const int h = sh & (NKV - 1);
        const int s = sh >> 3;
        const float c = rc[s * HD + d];
        const float sn = rc[s * HD + 32 + d];
        float* p = g_k + ((size_t)s * NKV + h) * HD;
        const float x1 = p[d], x2 = p[d + 32];
        p[d] = x1 * c - x2 * sn;
        p[d + 32] = x1 * sn + x2 * c;
    }
}

// ============================================================================
// Flash attention with TF32 tensor cores.
// Block: 128 thr (4 warps), 64 query rows (16/warp), 64-key tiles.
// Smem (dynamic): Ks[64][68] (key,dim), Vs[64][68] (dim,key  TRANSPOSED),
//                 Ps[64][68] (Q staging, then per-warp P tiles). stride 68
//                 makes fragment LDS bank-bijective.
// ============================================================================
#define FSTR 68

__global__ void __launch_bounds__(128, 3) flash_tc(const float* __restrict__ sinks)
{
    extern __shared__ uint32_t fsm[];
    uint32_t* Ks = fsm;
    uint32_t* Vs = fsm + 64 * FSTR;
    uint32_t* Ps = fsm + 2 * 64 * FSTR;

    const int h = blockIdx.y;
    const int kvh = h >> 2;
    const int qt = (int)gridDim.x - 1 - (int)blockIdx.x;   // heaviest first
    const int q0 = qt * 64;
    const int tid = threadIdx.x;
    const int w = tid >> 5;
    const int l = tid & 31;
    const int l4 = l >> 2;
    const int lk = l & 3;

    // ---- stage Q tile (scaled, tf32) through Ps, pick up a-fragments ----
    #pragma unroll
    for (int it = 0; it < 8; it++) {
        const int e = tid + it * 128;
        const int row = e >> 4, c4 = e & 15;
        float4 t = *(const float4*)(g_q + (size_t)(q0 + row) * (NH * HD) + h * HD + c4 * 4);
        uint32_t* p = Ps + row * FSTR + c4 * 4;
        p[0] = f2tf32(t.x * QK_SCALE);
        p[1] = f2tf32(t.y * QK_SCALE);
        p[2] = f2tf32(t.z * QK_SCALE);
        p[3] = f2tf32(t.w * QK_SCALE);
    }
    __syncthreads();

    uint32_t qf[8][4];
    #pragma unroll
    for (int kc = 0; kc < 8; kc++) {
        const uint32_t* base = Ps + (w * 16 + l4) * FSTR + kc * 8 + lk;
        qf[kc][0] = base[0];
        qf[kc][1] = base[8 * FSTR];
        qf[kc][2] = base[4];
        qf[kc][3] = base[8 * FSTR + 4];
    }

    float o[8][4];
    #pragma unroll
    for (int i = 0; i < 8; i++)
        #pragma unroll
        for (int j = 0; j < 4; j++) o[i][j] = 0.f;
    float m0 = -1e30f, m1 = -1e30f, l0 = 0.f, l1 = 0.f;

    for (int jt = 0; jt <= qt; jt++) {
        const int j0 = jt * 64;
        __syncthreads();   // prev iteration's PV reads of Vs done
        // ---- load K (natural) and V (transposed) tiles ----
        #pragma unroll
        for (int it = 0; it < 8; it++) {
            const int e = tid + it * 128;
            const int row = e >> 4, c4 = e & 15;
            const size_t base = (size_t)(j0 + row) * (NKV * HD) + kvh * HD + c4 * 4;
            float4 kv = *(const float4*)(g_k + base);
            uint32_t* kp = Ks + row * FSTR + c4 * 4;
            kp[0] = f2tf32(kv.x); kp[1] = f2tf32(kv.y);
            kp[2] = f2tf32(kv.z); kp[3] = f2tf32(kv.w);
            float4 vv = *(const float4*)(g_v + base);
            Vs[(c4 * 4 + 0) * FSTR + row] = f2tf32(vv.x);
            Vs[(c4 * 4 + 1) * FSTR + row] = f2tf32(vv.y);
            Vs[(c4 * 4 + 2) * FSTR + row] = f2tf32(vv.z);
            Vs[(c4 * 4 + 3) * FSTR + row] = f2tf32(vv.w);
        }
        __syncthreads();

        // ---- S = Q K^T (16 rows x 64 keys per warp) ----
        float c[8][4];
        #pragma unroll
        for (int i = 0; i < 8; i++)
            #pragma unroll
            for (int j = 0; j < 4; j++) c[i][j] = 0.f;
        #pragma unroll
        for (int kc = 0; kc < 8; kc++) {
            #pragma unroll
            for (int nt = 0; nt < 8; nt++) {
                uint32_t b[2];
                const uint32_t* bb = Ks + (nt * 8 + l4) * FSTR + kc * 8 + lk;
                b[0] = bb[0];
                b[1] = bb[4];
                mma_tf32(c[nt], qf[kc], b);
            }
        }

        // ---- causal mask (diagonal tile only, q0 == j0) ----
        if (jt == qt) {
            const int row0 = w * 16 + l4, row1 = row0 + 8;
            #pragma unroll
            for (int nt = 0; nt < 8; nt++) {
                const int col = nt * 8 + lk * 2;
                if (col > row0)     c[nt][0] = -1e30f;
                if (col + 1 > row0) c[nt][1] = -1e30f;
                if (col > row1)     c[nt][2] = -1e30f;
                if (col + 1 > row1) c[nt][3] = -1e30f;
            }
        }

        // ---- online softmax (rows l4 and l4+8 of warp tile) ----
        float rmax0 = -1e30f, rmax1 = -1e30f;
        #pragma unroll
        for (int nt = 0; nt < 8; nt++) {
            rmax0 = fmaxf(rmax0, fmaxf(c[nt][0], c[nt][1]));
            rmax1 = fmaxf(rmax1, fmaxf(c[nt][2], c[nt][3]));
        }
        rmax0 = fmaxf(rmax0, __shfl_xor_sync(0xffffffffu, rmax0, 1));
        rmax0 = fmaxf(rmax0, __shfl_xor_sync(0xffffffffu, rmax0, 2));
        rmax1 = fmaxf(rmax1, __shfl_xor_sync(0xffffffffu, rmax1, 1));
        rmax1 = fmaxf(rmax1, __shfl_xor_sync(0xffffffffu, rmax1, 2));

        const float mn0 = fmaxf(m0, rmax0);
        const float mn1 = fmaxf(m1, rmax1);
        const float al0 = __expf(m0 - mn0);
        const float al1 = __expf(m1 - mn1);
        m0 = mn0; m1 = mn1;

        float rs0 = 0.f, rs1 = 0.f;
        #pragma unroll
        for (int nt = 0; nt < 8; nt++) {
            c[nt][0] = __expf(c[nt][0] - mn0); rs0 += c[nt][0];
            c[nt][1] = __expf(c[nt][1] - mn0); rs0 += c[nt][1];
            c[nt][2] = __expf(c[nt][2] - mn1); rs1 += c[nt][2];
            c[nt][3] = __expf(c[nt][3] - mn1); rs1 += c[nt][3];
        }
        rs0 += __shfl_xor_sync(0xffffffffu, rs0, 1);
        rs0 += __shfl_xor_sync(0xffffffffu, rs0, 2);
        rs1 += __shfl_xor_sync(0xffffffffu, rs1, 1);
        rs1 += __shfl_xor_sync(0xffffffffu, rs1, 2);
        l0 = l0 * al0 + rs0;
        l1 = l1 * al1 + rs1;

        #pragma unroll
        for (int nt = 0; nt < 8; nt++) {
            o[nt][0] *= al0; o[nt][1] *= al0;
            o[nt][2] *= al1; o[nt][3] *= al1;
        }

        // ---- P -> smem (per-warp 16-row region of Ps), then O += P V ----
        {
            const int r0 = (w * 16 + l4) * FSTR, r1 = (w * 16 + l4 + 8) * FSTR;
            #pragma unroll
            for (int nt = 0; nt < 8; nt++) {
                const int col = nt * 8 + lk * 2;
                Ps[r0 + col]     = f2tf32(c[nt][0]);
                Ps[r0 + col + 1] = f2tf32(c[nt][1]);
                Ps[r1 + col]     = f2tf32(c[nt][2]);
                Ps[r1 + col + 1] = f2tf32(c[nt][3]);
            }
        }
        __syncwarp();

        #pragma unroll
        for (int kc = 0; kc < 8; kc++) {
            uint32_t pf[4];
            const uint32_t* base = Ps + (w * 16 + l4) * FSTR + kc * 8 + lk;
            pf[0] = base[0];
            pf[1] = base[8 * FSTR];
            pf[2] = base[4];
            pf[3] = base[8 * FSTR + 4];
            #pragma unroll
            for (int nt = 0; nt < 8; nt++) {
                uint32_t b[2];
                const uint32_t* bb = Vs + (nt * 8 + l4) * FSTR + kc * 8 + lk;
                b[0] = bb[0];
                b[1] = bb[4];
                mma_tf32(o[nt], pf, b);
            }
        }
        __syncwarp();   // P reads done before next tile's P store
    }

    // ---- epilogue: lse, sink sigmoid, normalize, store ----
    const float sk = sinks[h];
    const float lse0 = m0 + __logf(l0);
    const float lse1 = m1 + __logf(l1);
    const float w0 = (1.f / (1.f + __expf(sk - lse0))) / l0;
    const float w1 = (1.f / (1.f + __expf(sk - lse1))) / l1;
    const int row0 = q0 + w * 16 + l4;
    #pragma unroll
    for (int nt = 0; nt < 8; nt++) {
        const int col = h * HD + nt * 8 + lk * 2;
        float2 v0 = make_float2(o[nt][0] * w0, o[nt][1] * w0);
        float2 v1 = make_float2(o[nt][2] * w1, o[nt][3] * w1);
        *(float2*)(g_o + (size_t)row0 * (NH * HD) + col) = v0;
        *(float2*)(g_o + (size_t)(row0 + 8) * (NH * HD) + col) = v1;
    }
}

// ============================================================================
// launch
// ============================================================================
extern "C" void kernel_launch(void* const* d_in, const int* in_sizes, int n_in,
                              void* d_out, int out_size)
{
    const float* x     = (const float*)d_in[0];
    const float* rc    = (const float*)d_in[1];
    const float* wq_w  = (const float*)d_in[2];
    const float* wq_b  = (const float*)d_in[3];
    const float* wk_w  = (const float*)d_in[4];
    const float* wk_b  = (const float*)d_in[5];
    const float* wv_w  = (const float*)d_in[6];
    const float* wv_b  = (const float*)d_in[7];
    const float* wo_w  = (const float*)d_in[8];
    const float* wo_b  = (const float*)d_in[9];
    const float* sinks = (const float*)d_in[10];
    float* out = (float*)d_out;

    float *qp, *kp, *vp, *op;
    cudaGetSymbolAddress((void**)&qp, g_q);
    cudaGetSymbolAddress((void**)&kp, g_k);
    cudaGetSymbolAddress((void**)&vp, g_v);
    cudaGetSymbolAddress((void**)&op, g_o);

    static bool attr_done = false;
    if (!attr_done) {
        cudaFuncSetAttribute(flash_tc, cudaFuncAttributeMaxDynamicSharedMemorySize,
                             3 * 64 * FSTR * 4);
        attr_done = true;
    }

    // Q projection
    gemm_tf32_single<<<dim3((NH * HD) / 128, S_LEN / 128), 256>>>(x, wq_w, wq_b, qp, NH * HD, DIM);
    // fused K+V projections (fills the chip: 128 blocks)
    gemm_tf32_kv<<<dim3((NKV * HD) / 128, S_LEN / 128, 2), 256>>>(
        x, wk_w, wk_b, kp, wv_w, wv_b, vp, NKV * HD, DIM);

    // RoPE
    {
        const int total = S_LEN * NH * 32 + S_LEN * NKV * 32;
        rope_kernel<<<(total + 255) / 256, 256>>>(rc);
    }

    // flash attention (tf32 tensor cores)
    flash_tc<<<dim3(S_LEN / 64, NH), 128, 3 * 64 * FSTR * 4>>>(sinks);

    // output projection
    gemm_tf32_single<<<dim3(DIM / 128, S_LEN / 128), 256>>>(op, wo_w, wo_b, out, DIM, DIM);
}